// round 17
// baseline (speedup 1.0000x reference)
#include <cuda_runtime.h>
#include <cuda_fp16.h>
#include <cstdint>

// ============================================================================
// out[b,c] = sum_d W[c,d] * (softmax(mod[b,:])[d] + 1) * x[b,d]
// B=8192, D=1024, C=4096, fp32.
// R12: test 3 warps/SMSP. GEMM CTA 128x128x64, 4 warps (64x64), 2-stage
// cp.async, single-buffered frags, 3 CTAs/SM (regs capped ~170).
// Prologue: 128-thr MLP=4 (R11).
// ============================================================================

#define Bq 8192
#define Dq 1024
#define Cq 4096

#define BM 128
#define BN 128
#define BK 64
#define NT (Dq / BK)        // 16 k-tiles
#define STAGES 2
#define LDH 72              // BK + 8 pad halfs: 144B row stride, conflict-free

#define A_TILE_HALFS (BM * LDH)             // 9216
#define B_TILE_HALFS (BN * LDH)             // 9216
#define STAGE_BYTES ((A_TILE_HALFS + B_TILE_HALFS) * 2)   // 36864
#define SMEM_BYTES (STAGES * STAGE_BYTES)   // 73728 -> 3 CTAs/SM (221KB)

#define W_CTAS 2048

__device__ __half g_y[(size_t)Bq * Dq];
__device__ __half g_w[(size_t)Cq * Dq];

__device__ __forceinline__ uint32_t smem_u32(const void* p) {
    uint32_t a;
    asm("{ .reg .u64 t; cvta.to.shared.u64 t, %1; cvt.u32.u64 %0, t; }" : "=r"(a) : "l"(p));
    return a;
}

__device__ __forceinline__ void cp_async16(uint32_t dst, const void* src) {
    asm volatile("cp.async.cg.shared.global [%0], [%1], 16;" :: "r"(dst), "l"(src) : "memory");
}
#define CP_COMMIT() asm volatile("cp.async.commit_group;" ::: "memory")
#define CP_WAIT(n)  asm volatile("cp.async.wait_group %0;" :: "n"(n) : "memory")

#define LDM_X4(r0, r1, r2, r3, addr) \
    asm volatile("ldmatrix.sync.aligned.m8n8.x4.shared.b16 {%0,%1,%2,%3}, [%4];" \
                 : "=r"(r0), "=r"(r1), "=r"(r2), "=r"(r3) : "r"(addr))

__device__ __forceinline__ void mma_fp16(float c[4], uint32_t a0, uint32_t a1,
                                         uint32_t a2, uint32_t a3,
                                         uint32_t b0, uint32_t b1) {
    asm volatile(
        "mma.sync.aligned.m16n8k16.row.col.f32.f16.f16.f32 "
        "{%0,%1,%2,%3}, {%4,%5,%6,%7}, {%8,%9}, {%0,%1,%2,%3};"
        : "+f"(c[0]), "+f"(c[1]), "+f"(c[2]), "+f"(c[3])
        : "r"(a0), "r"(a1), "r"(a2), "r"(a3), "r"(b0), "r"(b1));
}

// ---------------------------------------------------------------------------
// Prologue, 128-thread CTAs, MLP=4 (unchanged from R11).
// ---------------------------------------------------------------------------
__global__ __launch_bounds__(128) void prologue_kernel(
    const float* __restrict__ x, const float* __restrict__ mod,
    const float* __restrict__ W,
    __half* __restrict__ y, __half* __restrict__ w16)
{
    const int t = threadIdx.x;
    if (blockIdx.x >= Bq) {
        size_t base = (size_t)(blockIdx.x - Bq) * (128 * 4) + t;
        const float4* src = reinterpret_cast<const float4*>(W);
        uint2* dst = reinterpret_cast<uint2*>(w16);
        float4 v0 = src[base];
        float4 v1 = src[base + 128];
        float4 v2 = src[base + 256];
        float4 v3 = src[base + 384];
        #pragma unroll
        for (int i = 0; i < 4; i++) {
            float4 v = (i == 0) ? v0 : (i == 1) ? v1 : (i == 2) ? v2 : v3;
            __half2 h0 = __floats2half2_rn(v.x, v.y);
            __half2 h1 = __floats2half2_rn(v.z, v.w);
            dst[base + i * 128] = make_uint2(*reinterpret_cast<uint32_t*>(&h0),
                                             *reinterpret_cast<uint32_t*>(&h1));
        }
        return;
    }

    const int b = blockIdx.x;
    const float4* mrow = reinterpret_cast<const float4*>(mod + (size_t)b * Dq);
    const float4* xrow = reinterpret_cast<const float4*>(x + (size_t)b * Dq);
    const float4 ma = mrow[t];
    const float4 mb = mrow[t + 128];
    const float4 xa = xrow[t];
    const float4 xb = xrow[t + 128];

    float mx = fmaxf(fmaxf(fmaxf(ma.x, ma.y), fmaxf(ma.z, ma.w)),
                     fmaxf(fmaxf(mb.x, mb.y), fmaxf(mb.z, mb.w)));
    #pragma unroll
    for (int o = 16; o; o >>= 1) mx = fmaxf(mx, __shfl_xor_sync(0xffffffffu, mx, o));

    __shared__ float sred[4];
    int w = t >> 5, l = t & 31;
    if (l == 0) sred[w] = mx;
    __syncthreads();
    float gmx = fmaxf(fmaxf(sred[0], sred[1]), fmaxf(sred[2], sred[3]));
    __syncthreads();

    float ea0 = expf(ma.x - gmx), ea1 = expf(ma.y - gmx);
    float ea2 = expf(ma.z - gmx), ea3 = expf(ma.w - gmx);
    float eb0 = expf(mb.x - gmx), eb1 = expf(mb.y - gmx);
    float eb2 = expf(mb.z - gmx), eb3 = expf(mb.w - gmx);
    float s = (ea0 + ea1 + ea2 + ea3) + (eb0 + eb1 + eb2 + eb3);
    #pragma unroll
    for (int o = 16; o; o >>= 1) s += __shfl_xor_sync(0xffffffffu, s, o);
    if (l == 0) sred[w] = s;
    __syncthreads();
    float inv = 1.0f / (sred[0] + sred[1] + sred[2] + sred[3]);

    uint2* yrow = reinterpret_cast<uint2*>(y + (size_t)b * Dq);
    {
        __half2 h0 = __floats2half2_rn(fmaf(ea0, inv, 1.0f) * xa.x,
                                       fmaf(ea1, inv, 1.0f) * xa.y);
        __half2 h1 = __floats2half2_rn(fmaf(ea2, inv, 1.0f) * xa.z,
                                       fmaf(ea3, inv, 1.0f) * xa.w);
        yrow[t] = make_uint2(*reinterpret_cast<uint32_t*>(&h0),
                             *reinterpret_cast<uint32_t*>(&h1));
    }
    {
        __half2 h0 = __floats2half2_rn(fmaf(eb0, inv, 1.0f) * xb.x,
                                       fmaf(eb1, inv, 1.0f) * xb.y);
        __half2 h1 = __floats2half2_rn(fmaf(eb2, inv, 1.0f) * xb.z,
                                       fmaf(eb3, inv, 1.0f) * xb.w);
        yrow[t + 128] = make_uint2(*reinterpret_cast<uint32_t*>(&h0),
                                   *reinterpret_cast<uint32_t*>(&h1));
    }
}

// ---------------------------------------------------------------------------
// GEMM: out = y @ W^T. CTA 128x128x64, 128 threads, 4 warps 2(m) x 2(n),
// warp tile 64x64. 2-stage cp.async, single-buffered frags, 3 CTAs/SM.
// ---------------------------------------------------------------------------
__global__ __launch_bounds__(128, 3) void gemm_fp16_kernel(
    const __half* __restrict__ A,   // g_y  [B][D]
    const __half* __restrict__ Bw,  // g_w  [C][D]
    float* __restrict__ out)        // [B][C]
{
    extern __shared__ __half smem[];
    const uint32_t sbase = smem_u32(smem);
    const int tid  = threadIdx.x;
    const int wid  = tid >> 5;
    const int lane = tid & 31;
    const int m0 = blockIdx.y * BM;
    const int n0 = blockIdx.x * BN;
    const int warp_m = wid >> 1;   // 0..1
    const int warp_n = wid & 1;    // 0..1

    const int ldrow = tid >> 3;       // 0..15
    const int ldch  = (tid & 7) * 8;  // half-offset of 16B chunk
    auto load_tile = [&](int s, int kt) {
        const int k0 = kt * BK;
        const uint32_t sA = sbase + (uint32_t)(s * STAGE_BYTES);
        const uint32_t sB = sA + A_TILE_HALFS * 2u;
        #pragma unroll
        for (int i = 0; i < 8; i++) {
            int r = ldrow + 16 * i;
            cp_async16(sA + (uint32_t)(r * LDH + ldch) * 2u,
                       A + (size_t)(m0 + r) * Dq + k0 + ldch);
        }
        #pragma unroll
        for (int i = 0; i < 8; i++) {
            int r = ldrow + 16 * i;
            cp_async16(sB + (uint32_t)(r * LDH + ldch) * 2u,
                       Bw + (size_t)(n0 + r) * Dq + k0 + ldch);
        }
    };

    float acc[4][8][4];
    #pragma unroll
    for (int mt = 0; mt < 4; mt++)
        #pragma unroll
        for (int nt = 0; nt < 8; nt++)
            #pragma unroll
            for (int i = 0; i < 4; i++) acc[mt][nt][i] = 0.0f;

    // prefetch stage 0
    load_tile(0, 0);
    CP_COMMIT();

    const int lrow = lane & 15;
    const int kh   = (lane >> 4) * 8;
    const uint32_t offA0 = (uint32_t)((warp_m * 64 + lrow) * LDH + kh);
    const uint32_t offB0 = (uint32_t)((warp_n * 64 + lrow) * LDH + kh);

    const int fr = lane >> 2;
    const int fc = lane & 3;

    for (int kt = 0; kt < NT; kt++) {
        const int cur = kt & 1;
        CP_WAIT(0);            // tile kt resident
        __syncthreads();       // all warps done with the other stage
        if (kt + 1 < NT) {     // prefetch next tile into the other stage
            load_tile(cur ^ 1, kt + 1);
            CP_COMMIT();
        }

        const uint32_t sA = sbase + (uint32_t)(cur * STAGE_BYTES);
        const uint32_t sB = sA + A_TILE_HALFS * 2u;

        #pragma unroll
        for (int ks = 0; ks < 4; ks++) {
            uint32_t af[4][4];
            #pragma unroll
            for (int mt = 0; mt < 4; mt++) {
                uint32_t addr = sA + (offA0 + (uint32_t)(mt * 16 * LDH + ks * 16)) * 2u;
                LDM_X4(af[mt][0], af[mt][1], af[mt][2], af[mt][3], addr);
            }
            #pragma unroll
            for (int np = 0; np < 4; np++) {   // B pair covers nt = 2np, 2np+1
                uint32_t b00, b10, b01, b11;
                uint32_t addr = sB + (offB0 + (uint32_t)(np * 16 * LDH + ks * 16)) * 2u;
                LDM_X4(b00, b10, b01, b11, addr);
                #pragma unroll
                for (int mt = 0; mt < 4; mt++) {
                    mma_fp16(acc[mt][2 * np],     af[mt][0], af[mt][1], af[mt][2], af[mt][3], b00, b01);
                    mma_fp16(acc[mt][2 * np + 1], af[mt][0], af[mt][1], af[mt][2], af[mt][3], b10, b11);
                }
            }
        }
        __syncthreads();       // done reading stage cur before it is refilled
    }

    // --- epilogue: float2 stores ---
    #pragma unroll
    for (int mt = 0; mt < 4; mt++) {
        int rg = m0 + warp_m * 64 + mt * 16 + fr;
        #pragma unroll
        for (int nt = 0; nt < 8; nt++) {
            int cg = n0 + warp_n * 64 + nt * 8 + fc * 2;
            float2* p0 = reinterpret_cast<float2*>(out + (size_t)rg * Cq + cg);
            float2* p1 = reinterpret_cast<float2*>(out + (size_t)(rg + 8) * Cq + cg);
            *p0 = make_float2(acc[mt][nt][0], acc[mt][nt][1]);
            *p1 = make_float2(acc[mt][nt][2], acc[mt][nt][3]);
        }
    }
}

// ---------------------------------------------------------------------------
// Host launcher
// ---------------------------------------------------------------------------
extern "C" void kernel_launch(void* const* d_in, const int* in_sizes, int n_in,
                              void* d_out, int out_size)
{
    const float* x   = (const float*)d_in[0];
    const float* mod = (const float*)d_in[1];
    const float* W   = (const float*)d_in[2];
    float* out = (float*)d_out;

    __half* yptr = nullptr;
    __half* wptr = nullptr;
    cudaGetSymbolAddress((void**)&yptr, g_y);
    cudaGetSymbolAddress((void**)&wptr, g_w);

    prologue_kernel<<<Bq + W_CTAS, 128>>>(x, mod, W, yptr, wptr);

    cudaFuncSetAttribute(gemm_fp16_kernel,
                         cudaFuncAttributeMaxDynamicSharedMemorySize, SMEM_BYTES);
    dim3 grid(Cq / BN, Bq / BM);   // (32, 64) = 2048 CTAs
    gemm_fp16_kernel<<<grid, 128, SMEM_BYTES>>>(yptr, wptr, out);
}